// round 17
// baseline (speedup 1.0000x reference)
#include <cuda_runtime.h>
#include <cuda_fp16.h>
#include <cstdint>

// ---------------- problem constants ----------------
#define N_NODES 8192
#define DFEAT   128
#define EPS     1e-6f

// ---------------- GEMM tiling ----------------
#define BM       128
#define KITEM    2048                   // K per work item (split-K = 4)
#define KSTAGE   64
#define NSTAGES  (KITEM / KSTAGE)       // 32
#define ROWB     144                    // smem row stride bytes (64 fp16 = 128B + 16 pad)
#define ATILE    (BM * ROWB)            // 18432
#define BTILE    (DFEAT * ROWB)         // 18432
#define BUFB     (ATILE + BTILE)        // 36864
#define NPIPE    3
#define SMEM_DYN (NPIPE * BUFB)         // 110592

#define NCTA      128
#define NTHREADS  640                   // 16 GEMM warps + 4 rowsum warps

// ---------------- scratch (no allocation allowed) ----------------
__device__ float                   g_dinv[N_NODES];
__device__ __align__(16) __half    g_adjh[(size_t)N_NODES * N_NODES]; // fp16 adj (128 MB)
__device__ __align__(16) __half    g_y[DFEAT * N_NODES];              // [c][k] fp16, unscaled xW^T
__device__ __align__(16) __half    g_zs[DFEAT * N_NODES];             // [c][k] fp16, dinv[k]-scaled
__device__ __align__(16) float     g_part[4][N_NODES * DFEAT];        // 16 MB split-K partials
__device__ unsigned                g_cnt[128];                        // rows-done per 64-row granule

// ---------------- helpers ----------------
static __device__ __forceinline__ uint32_t smem_u32(const void* p) {
    uint32_t a;
    asm("{ .reg .u64 t; cvta.to.shared.u64 t, %1; cvt.u32.u64 %0, t; }" : "=r"(a) : "l"(p));
    return a;
}

#define LDSM4(r, addr) \
    asm volatile("ldmatrix.sync.aligned.m8n8.x4.shared.b16 {%0,%1,%2,%3}, [%4];" \
        : "=r"((r)[0]), "=r"((r)[1]), "=r"((r)[2]), "=r"((r)[3]) : "r"(addr))

#define MMAF16(d, a, b0, b1) \
    asm volatile("mma.sync.aligned.m16n8k16.row.col.f32.f16.f16.f32 " \
        "{%0,%1,%2,%3}, {%4,%5,%6,%7}, {%8,%9}, {%0,%1,%2,%3};" \
        : "+f"((d)[0]), "+f"((d)[1]), "+f"((d)[2]), "+f"((d)[3]) \
        : "r"((a)[0]), "r"((a)[1]), "r"((a)[2]), "r"((a)[3]), "r"(b0), "r"(b1))

#define CPASYNC16(dst, src) \
    asm volatile("cp.async.cg.shared.global [%0], [%1], 16;" :: "r"(dst), "l"(src))
#define CP_COMMIT() asm volatile("cp.async.commit_group;" ::: "memory")
#define CP_WAIT1()  asm volatile("cp.async.wait_group 1;" ::: "memory")
#define CP_WAIT0()  asm volatile("cp.async.wait_group 0;" ::: "memory")
#define BAR2()      asm volatile("bar.sync 2, 512;" ::: "memory")

static __device__ __forceinline__ uint2 f4_to_h4(float4 v) {
    __half2 p0 = __float22half2_rn(make_float2(v.x, v.y));
    __half2 p1 = __float22half2_rn(make_float2(v.z, v.w));
    uint2 r;
    r.x = *reinterpret_cast<uint32_t*>(&p0);
    r.y = *reinterpret_cast<uint32_t*>(&p1);
    return r;
}

// Reader-side gate: lane 0 spins until cnt[f] == 64, then acquire-fence.
static __device__ __forceinline__ void wait_cnt(const unsigned* cnt, int f) {
    if ((threadIdx.x & 31) == 0) {
        volatile const unsigned* p = cnt + f;
        while (*p < 64u) __nanosleep(128);
    }
    __syncwarp();
    __threadfence();   // order flag read before subsequent data reads
}

// ---------------------------------------------------------------------------
// Kernel 0: reset progress counters (must run every launch / graph replay)
// ---------------------------------------------------------------------------
__global__ void reset_kernel(unsigned* cnt) {
    cnt[threadIdx.x] = 0u;
}

// ---------------------------------------------------------------------------
// Kernel 1: y[c][k] = fp16( dot(x[k,:], W[c,:]) )   (fp32 math, NO dinv)
// ---------------------------------------------------------------------------
__global__ __launch_bounds__(256) void xw_kernel(
    const float* __restrict__ x, const float* __restrict__ W,
    __half* __restrict__ y)
{
    __shared__ float xs[8][DFEAT];
    __shared__ float zsm[DFEAT][8];
    int r0 = blockIdx.x * 8;
    int t = threadIdx.x;
    for (int i = t; i < 8 * DFEAT; i += 256)
        xs[i >> 7][i & 127] = x[(size_t)r0 * DFEAT + i];
    __syncthreads();

    int c = t & 127, rh = t >> 7;
    const float4* wr = reinterpret_cast<const float4*>(W + (size_t)c * DFEAT);
    float acc[4] = {0.f, 0.f, 0.f, 0.f};
    #pragma unroll 8
    for (int k4 = 0; k4 < DFEAT / 4; k4++) {
        float4 wv = __ldg(&wr[k4]);
        #pragma unroll
        for (int j = 0; j < 4; j++) {
            const float* xr = &xs[rh * 4 + j][k4 * 4];
            acc[j] += wv.x * xr[0] + wv.y * xr[1] + wv.z * xr[2] + wv.w * xr[3];
        }
    }
    #pragma unroll
    for (int j = 0; j < 4; j++)
        zsm[c][rh * 4 + j] = acc[j];
    __syncthreads();

    if (t < 128) {
        uint2 h0 = f4_to_h4(make_float4(zsm[t][0], zsm[t][1], zsm[t][2], zsm[t][3]));
        uint2 h1 = f4_to_h4(make_float4(zsm[t][4], zsm[t][5], zsm[t][6], zsm[t][7]));
        *reinterpret_cast<uint4*>(y + (size_t)t * N_NODES + r0) = make_uint4(h0.x, h0.y, h1.x, h1.y);
    }
}

// ---------------------------------------------------------------------------
// Kernel 2 (MEGA): fused rowsum/convert/scale producer + fp16 MMA GEMM consumer.
// 128 CTAs x 640 threads. Warps 0-15: GEMM (2 split-K items each).
// Warps 16-19: stream rowsum -> dinv, adjh, zs; publish per-64-row counters.
// ---------------------------------------------------------------------------
__global__ __launch_bounds__(NTHREADS, 1) void mega_kernel(
    const float* __restrict__ adj,
    const __half* __restrict__ y,
    __half* __restrict__ adjh,
    __half* __restrict__ zs,
    float* __restrict__ dinv,
    unsigned* __restrict__ cnt,
    float* __restrict__ part)
{
    extern __shared__ char smem[];
    const int tid  = threadIdx.x;
    const int lane = tid & 31;
    const int wid  = tid >> 5;
    const int cta  = blockIdx.x;

    if (wid >= 16) {
        // ================= rowsum / producer warps =================
        const int rw = wid - 16;                  // 0..3
        for (int i = 0; i < 8; i++) {             // 8 waves -> global row order
            const int rbase = i * 1024 + cta * 8 + rw * 2;
            float dis[2];
            #pragma unroll
            for (int rr = 0; rr < 2; rr++) {
                const int r = rbase + rr;
                const float4* src = reinterpret_cast<const float4*>(adj + (size_t)r * N_NODES);
                uint2* dst = reinterpret_cast<uint2*>(adjh + (size_t)r * N_NODES);
                float s = 0.f;
                #pragma unroll 8
                for (int j = 0; j < 64; j++) {
                    float4 v = src[lane + j * 32];
                    s += (v.x + v.y) + (v.z + v.w);
                    dst[lane + j * 32] = f4_to_h4(v);
                }
                #pragma unroll
                for (int off = 16; off > 0; off >>= 1)
                    s += __shfl_xor_sync(0xffffffffu, s, off);
                float di = rsqrtf(s + EPS);
                if (lane == 0) dinv[r] = di;
                dis[rr] = di;
            }
            // scale B columns k = rbase, rbase+1 : zs[c][k] = dinv[k] * y[c][k]
            __half2 dh = __floats2half2_rn(dis[0], dis[1]);
            #pragma unroll
            for (int tci = 0; tci < 4; tci++) {
                int c = lane + tci * 32;
                uint32_t v = *reinterpret_cast<const uint32_t*>(y + (size_t)c * N_NODES + rbase);
                __half2 hv = *reinterpret_cast<__half2*>(&v);
                hv = __hmul2(hv, dh);
                *reinterpret_cast<uint32_t*>(zs + (size_t)c * N_NODES + rbase) =
                    *reinterpret_cast<uint32_t*>(&hv);
            }
            __threadfence();                       // release writes before count
            if (lane == 0) atomicAdd(&cnt[rbase >> 6], 2u);
        }
        return;
    }

    // ================= GEMM warps =================
    const uint32_t sbase = smem_u32(smem);
    const int wm = wid >> 2;            // 0..3
    const int wn = wid & 3;             // 0..3

    // ldmatrix address precompute (item-invariant)
    const int idx = lane >> 3;
    const uint32_t a_lm = (uint32_t)((wm * 32 + (idx & 1) * 8 + (lane & 7)) * ROWB + ((idx >> 1) * 8) * 2);
    const uint32_t b_lm = (uint32_t)((wn * 32 + (idx >> 1) * 8 + (lane & 7)) * ROWB + ((idx & 1) * 8) * 2);
    const uint32_t aSoff = (uint32_t)((tid >> 3) * ROWB + (tid & 7) * 16);

    for (int it = 0; it < 2; it++) {
        const int mt = (it == 0) ? (cta & 63) : ((cta & 63) ^ 32);
        const int q  = (it == 0) ? (cta >> 6) : (2 + (cta >> 6));
        const int m0 = mt * BM;
        const int k0 = q * KITEM;
        float* pout = part + (size_t)q * (N_NODES * DFEAT);

        // A-tile rows must be fully converted
        wait_cnt(cnt, 2 * mt);
        wait_cnt(cnt, 2 * mt + 1);

        const __half* aBase = adjh + (size_t)(m0 + (tid >> 3)) * N_NODES + k0 + ((tid & 7) << 3);
        const __half* bBase = zs + (size_t)(tid >> 3) * N_NODES + k0 + ((tid & 7) << 3);

        float d[2][4][4];
        #pragma unroll
        for (int a = 0; a < 2; a++)
            #pragma unroll
            for (int b = 0; b < 4; b++)
                #pragma unroll
                for (int qq = 0; qq < 4; qq++) d[a][b][qq] = 0.f;

        auto issue_stage = [&](int s) {
            const uint32_t sb = sbase + (uint32_t)((s % NPIPE) * BUFB);
            const int ko = s * KSTAGE;
            #pragma unroll
            for (int i = 0; i < 2; i++) {
                CPASYNC16(sb + aSoff + i * (64 * ROWB), aBase + (size_t)(i * 64) * N_NODES + ko);
                CPASYNC16(sb + ATILE + aSoff + i * (64 * ROWB), bBase + (size_t)(i * 64) * N_NODES + ko);
            }
        };

        wait_cnt(cnt, q * 32 + 0); issue_stage(0); CP_COMMIT();
        wait_cnt(cnt, q * 32 + 1); issue_stage(1); CP_COMMIT();

        for (int s = 0; s < NSTAGES; s++) {
            CP_WAIT1();       // stage s resident (pending: s+1)
            BAR2();           // all GEMM warps done with stage s-1
            if (s + 2 < NSTAGES) { wait_cnt(cnt, q * 32 + s + 2); issue_stage(s + 2); }
            CP_COMMIT();      // uniform group count

            const uint32_t sa  = sbase + (uint32_t)((s % NPIPE) * BUFB);
            const uint32_t sbm = sa + ATILE;
            #pragma unroll
            for (int kk = 0; kk < 4; kk++) {
                uint32_t af[2][4], bf[2][4];
                #pragma unroll
                for (int mf = 0; mf < 2; mf++)
                    LDSM4(af[mf], sa + a_lm + mf * (16 * ROWB) + kk * 32);
                #pragma unroll
                for (int nf = 0; nf < 2; nf++)
                    LDSM4(bf[nf], sbm + b_lm + nf * (16 * ROWB) + kk * 32);
                #pragma unroll
                for (int mf = 0; mf < 2; mf++)
                    #pragma unroll
                    for (int nfr = 0; nfr < 4; nfr++)
                        MMAF16(d[mf][nfr], af[mf], bf[nfr >> 1][(nfr & 1) * 2], bf[nfr >> 1][(nfr & 1) * 2 + 1]);
            }
        }

        CP_WAIT0();           // drain tail groups
        BAR2();               // all MMAs done before smem reuse by next item

        // epilogue: write partials (no dinv here; applied in reduce)
        const int g = lane >> 2, tg = lane & 3;
        #pragma unroll
        for (int mf = 0; mf < 2; mf++) {
            #pragma unroll
            for (int nf = 0; nf < 4; nf++) {
                int m = m0 + wm * 32 + mf * 16 + g;
                int n = wn * 32 + nf * 8 + tg * 2;
                float* o = pout + (size_t)m * DFEAT + n;
                *reinterpret_cast<float2*>(o) = make_float2(d[mf][nf][0], d[mf][nf][1]);
                *reinterpret_cast<float2*>(o + 8 * DFEAT) = make_float2(d[mf][nf][2], d[mf][nf][3]);
            }
        }
    }
}

// ---------------------------------------------------------------------------
// Kernel 3: out[m][c] = dinv[m] * (p0+p1+p2+p3)[m][c] + b[c]
// ---------------------------------------------------------------------------
__global__ void reduce_kernel(const float* __restrict__ part,
                              const float* __restrict__ dinv, const float* __restrict__ bias,
                              float* __restrict__ out)
{
    int idx = blockIdx.x * blockDim.x + threadIdx.x;
    int e = idx << 2;
    int m = e >> 7, c = e & 127;
    const size_t stride = (size_t)N_NODES * DFEAT / 4;
    float4 a = reinterpret_cast<const float4*>(part)[idx];
    float4 b = reinterpret_cast<const float4*>(part)[idx + stride];
    float4 p = reinterpret_cast<const float4*>(part)[idx + 2 * stride];
    float4 qv = reinterpret_cast<const float4*>(part)[idx + 3 * stride];
    float di = __ldg(&dinv[m]);
    float4 bb = *reinterpret_cast<const float4*>(bias + c);
    float4 o;
    o.x = di * (a.x + b.x + p.x + qv.x) + bb.x;
    o.y = di * (a.y + b.y + p.y + qv.y) + bb.y;
    o.z = di * (a.z + b.z + p.z + qv.z) + bb.z;
    o.w = di * (a.w + b.w + p.w + qv.w) + bb.w;
    reinterpret_cast<float4*>(out)[idx] = o;
}

// ---------------------------------------------------------------------------
// kernel_launch: inputs per metadata order: x, adj, W, b
// ---------------------------------------------------------------------------
extern "C" void kernel_launch(void* const* d_in, const int* in_sizes, int n_in,
                              void* d_out, int out_size) {
    const float* x   = (const float*)d_in[0];
    const float* adj = (const float*)d_in[1];
    const float* W   = (const float*)d_in[2];
    const float* b   = (const float*)d_in[3];
    float* out = (float*)d_out;

    float* dinv;   cudaGetSymbolAddress((void**)&dinv, g_dinv);
    __half* adjh;  cudaGetSymbolAddress((void**)&adjh, g_adjh);
    __half* y;     cudaGetSymbolAddress((void**)&y, g_y);
    __half* zs;    cudaGetSymbolAddress((void**)&zs, g_zs);
    float* part;   cudaGetSymbolAddress((void**)&part, g_part);
    unsigned* cnt; cudaGetSymbolAddress((void**)&cnt, g_cnt);

    cudaFuncSetAttribute(mega_kernel, cudaFuncAttributeMaxDynamicSharedMemorySize, SMEM_DYN);

    reset_kernel<<<1, 128>>>(cnt);
    xw_kernel<<<N_NODES / 8, 256>>>(x, W, y);
    mega_kernel<<<NCTA, NTHREADS, SMEM_DYN>>>(adj, y, adjh, zs, dinv, cnt, part);
    reduce_kernel<<<(N_NODES * DFEAT / 4) / 256, 256>>>(part, dinv, b, out);
}